// round 10
// baseline (speedup 1.0000x reference)
#include <cuda_runtime.h>

// Problem dims (fixed by reference setup_inputs)
#define B_DIM 8192
#define T_DIM 2048
#define H     20
#define CTA_ROWS 64       // batch rows per CTA = two 32-row half-recurrences
#define NTHR  320         // 10 warps; warp w = unit-pair w; lane = row-in-half
#define UPIN  12          // source units pinned in registers (96 regs)
#define HPAD  28          // h row padding (floats): 28l mod 32 distinct for l<8

typedef unsigned long long u64;

// Scratch (allocation-free rule: __device__ globals)
__device__ float g_xT[(size_t)T_DIM * B_DIM];   // x transposed: [t][b]
__device__ float g_outT[(size_t)T_DIM * B_DIM]; // out transposed: [t][b]

// ---------------- f32x2 helpers ----------------
__device__ __forceinline__ u64 pk(float lo, float hi) {
    u64 r; asm("mov.b64 %0,{%1,%2};" : "=l"(r) : "f"(lo), "f"(hi)); return r;
}
__device__ __forceinline__ void upk(u64 v, float& lo, float& hi) {
    asm("mov.b64 {%0,%1},%2;" : "=f"(lo), "=f"(hi) : "l"(v));
}
__device__ __forceinline__ u64 fma2(u64 a, u64 b, u64 c) {
    u64 d; asm("fma.rn.f32x2 %0,%1,%2,%3;" : "=l"(d) : "l"(a), "l"(b), "l"(c)); return d;
}
__device__ __forceinline__ float tanh_a(float x) {
    float r; asm("tanh.approx.f32 %0,%1;" : "=f"(r) : "f"(x)); return r;
}

// LSTM cell via MUFU.TANH: 5 MUFU + ~9 FMA-pipe ops.
// sigmoid(x) = 0.5*tanh(0.5x) + 0.5
__device__ __forceinline__ void cell(float ig, float fg, float gg, float og,
                                     float& c, float& h) {
    float si = fmaf(0.5f, tanh_a(0.5f * ig), 0.5f);
    float sf = fmaf(0.5f, tanh_a(0.5f * fg), 0.5f);
    float so = fmaf(0.5f, tanh_a(0.5f * og), 0.5f);
    float tg = tanh_a(gg);
    float cn = sf * c + si * tg;
    float tc = tanh_a(cn);
    c = cn;
    h = so * tc;
}

// ---------------- transposes ----------------
__global__ void transpose_in(const float* __restrict__ in) {
    __shared__ float tile[32][33];
    int c0 = blockIdx.x * 32, r0 = blockIdx.y * 32;
    int tx = threadIdx.x, ty = threadIdx.y;
#pragma unroll
    for (int i = 0; i < 32; i += 8)
        tile[ty + i][tx] = in[(size_t)(r0 + ty + i) * T_DIM + c0 + tx];
    __syncthreads();
#pragma unroll
    for (int i = 0; i < 32; i += 8)
        g_xT[(size_t)(c0 + ty + i) * B_DIM + r0 + tx] = tile[tx][ty + i];
}

__global__ void transpose_out(float* __restrict__ out) {
    __shared__ float tile[32][33];
    int c0 = blockIdx.x * 32, r0 = blockIdx.y * 32;
    int tx = threadIdx.x, ty = threadIdx.y;
#pragma unroll
    for (int i = 0; i < 32; i += 8)
        tile[ty + i][tx] = g_outT[(size_t)(r0 + ty + i) * B_DIM + c0 + tx];
    __syncthreads();
#pragma unroll
    for (int i = 0; i < 32; i += 8)
        out[(size_t)(c0 + ty + i) * T_DIM + r0 + tx] = tile[tx][ty + i];
}

// ---------------- main persistent LSTM kernel ----------------
// 128 CTAs x 320 threads (10 warps). CTA = two independent 32-row halves.
// Warp up owns UNIT PAIR {2up, 2up+1}. Per phase, lane = row within the half;
// f32x2 packs (unit a, unit b). The two phases touch disjoint state and have
// NO barrier between them -> ptxas interleaves phase-B loads/FMAs into
// phase-A's cell-chain and LDS latency shadows (2x ILP on the latency chains).
// One __syncthreads per step; h double-buffered; UPIN units register-pinned.
__global__ __launch_bounds__(NTHR, 1) void lstm_kernel(
    const float* __restrict__ W1, const float* __restrict__ b1,
    const float* __restrict__ W_ih, const float* __restrict__ W_hh,
    const float* __restrict__ b_ih, const float* __restrict__ b_hh,
    const float* __restrict__ W2, const float* __restrict__ b2)
{
    // WP_s[u][up*4 + g] = (W_hh[g*H+2up][u], W_hh[g*H+2up+1][u])
    __shared__ __align__(16) u64 WP_s[H][40];        // 6.4 KB
    __shared__ __align__(16) u64 uvz[80];            // [p*8+2g]=u-pair, [+1]=v-pair
    __shared__ u64 w2q[10];                          // (W2[2j], W2[2j+1])
    __shared__ float b2_s;
    // h[buf][half][row][unit], unit-dim padded to HPAD -> 5 conflict-free
    // LDS.128 per row; STS.64 per warp per phase.
    __shared__ __align__(16) float h_s[2][2][32][HPAD];

    const int tid  = threadIdx.x;
    const int lane = tid & 31;
    const int up   = tid >> 5;                       // unit pair index 0..9
    const int up4  = up * 4;
    const int rowbase = blockIdx.x * CTA_ROWS;
    const int rowA = rowbase + lane;                 // phase-A global row
    const int rowB = rowbase + 32 + lane;            // phase-B global row

    // --- one-time setup ---
    for (int i = tid; i < H * 40; i += NTHR) {
        int u = i / 40, j = i % 40;
        int p = j >> 2, g = j & 3;                   // unit pair p, gate g
        float wa = W_hh[(g * H + 2 * p    ) * H + u];
        float wb = W_hh[(g * H + 2 * p + 1) * H + u];
        WP_s[u][j] = pk(wa, wb);
    }
    if (tid < 40) {
        int p = tid >> 2, g = tid & 3;
        float su[2], sv[2];
#pragma unroll
        for (int s = 0; s < 2; ++s) {
            int k = g * H + 2 * p + s;               // original gate-row index
            float a = 0.f, bsum = 0.f;
            for (int u = 0; u < H; ++u) {
                float wv = W_ih[k * H + u];
                a    += wv * W1[u];
                bsum += wv * b1[u];
            }
            su[s] = a;
            sv[s] = bsum + b_ih[k] + b_hh[k];
        }
        uvz[p * 8 + 2 * g]     = pk(su[0], su[1]);
        uvz[p * 8 + 2 * g + 1] = pk(sv[0], sv[1]);
    }
    if (tid < 10) w2q[tid] = pk(W2[2 * tid], W2[2 * tid + 1]);
    if (tid == 0) b2_s = b2[0];
    for (int i = tid; i < 2 * 2 * 32 * HPAD; i += NTHR)
        (&h_s[0][0][0][0])[i] = 0.f;
    __syncthreads();

    // loop-invariant input-path coefficient pairs
    const u64 u_i = uvz[up * 8 + 0], v_i = uvz[up * 8 + 1];
    const u64 u_f = uvz[up * 8 + 2], v_f = uvz[up * 8 + 3];
    const u64 u_g = uvz[up * 8 + 4], v_g = uvz[up * 8 + 5];
    const u64 u_o = uvz[up * 8 + 6], v_o = uvz[up * 8 + 7];

    // PIN weights for source units [0, UPIN): 8 regs per unit
    ulonglong2 wpa[UPIN], wpb[UPIN];
#pragma unroll
    for (int u = 0; u < UPIN; ++u) {
        wpa[u] = *(const ulonglong2*)&WP_s[u][up4];       // (w_i, w_f)
        wpb[u] = *(const ulonglong2*)&WP_s[u][up4 + 2];   // (w_g, w_o)
    }

    u64 cA = 0ULL, cB = 0ULL;   // cell state (u0,u1): phase A row, phase B row

    float xA = g_xT[rowA];
    float xB = g_xT[rowB];

    for (int t = 0; t < T_DIM; ++t) {
        const int cur = t & 1, nxt = cur ^ 1;

        float xAn = xA, xBn = xB;
        if (t + 1 < T_DIM) {
            xAn = g_xT[(size_t)(t + 1) * B_DIM + rowA];
            xBn = g_xT[(size_t)(t + 1) * B_DIM + rowB];
        }

        // ================= phase A (rows 0-31) =================
        {
            const float* hr = &h_s[cur][0][lane][0];
            float4 q0 = *(const float4*)(hr +  0);
            float4 q1 = *(const float4*)(hr +  4);
            float4 q2 = *(const float4*)(hr +  8);
            float4 q3 = *(const float4*)(hr + 12);
            float4 q4 = *(const float4*)(hr + 16);
            float hv[20] = {q0.x,q0.y,q0.z,q0.w, q1.x,q1.y,q1.z,q1.w,
                            q2.x,q2.y,q2.z,q2.w, q3.x,q3.y,q3.z,q3.w,
                            q4.x,q4.y,q4.z,q4.w};

            if (up == 0 && t > 0) {               // out[t-1] for row A
                u64 oa = 0ULL;
#pragma unroll
                for (int j = 0; j < 10; ++j)
                    oa = fma2(w2q[j], pk(hv[2*j], hv[2*j+1]), oa);
                float lo, hi; upk(oa, lo, hi);
                g_outT[(size_t)(t - 1) * B_DIM + rowA] = lo + hi + b2_s;
            }

            u64 x2 = pk(xA, xA);
            u64 ai = fma2(x2, u_i, v_i), af = fma2(x2, u_f, v_f);
            u64 ag = fma2(x2, u_g, v_g), ao = fma2(x2, u_o, v_o);
#pragma unroll
            for (int u = 0; u < UPIN; ++u) {
                u64 hp = pk(hv[u], hv[u]);
                ai = fma2(wpa[u].x, hp, ai);  af = fma2(wpa[u].y, hp, af);
                ag = fma2(wpb[u].x, hp, ag);  ao = fma2(wpb[u].y, hp, ao);
            }
#pragma unroll
            for (int u = UPIN; u < H; ++u) {
                u64 hp = pk(hv[u], hv[u]);
                ulonglong2 wa = *(const ulonglong2*)&WP_s[u][up4];
                ulonglong2 wb = *(const ulonglong2*)&WP_s[u][up4 + 2];
                ai = fma2(wa.x, hp, ai);  af = fma2(wa.y, hp, af);
                ag = fma2(wb.x, hp, ag);  ao = fma2(wb.y, hp, ao);
            }
            float i0,i1,f0,f1,g0,g1,o0,o1;
            upk(ai,i0,i1); upk(af,f0,f1); upk(ag,g0,g1); upk(ao,o0,o1);
            float c0,c1; upk(cA,c0,c1);
            float h0,h1;
            cell(i0,f0,g0,o0,c0,h0);
            cell(i1,f1,g1,o1,c1,h1);
            cA = pk(c0,c1);
            *(u64*)&h_s[nxt][0][lane][2*up] = pk(h0,h1);
        }

        // ================= phase B (rows 32-63) — independent ==========
        {
            const float* hr = &h_s[cur][1][lane][0];
            float4 q0 = *(const float4*)(hr +  0);
            float4 q1 = *(const float4*)(hr +  4);
            float4 q2 = *(const float4*)(hr +  8);
            float4 q3 = *(const float4*)(hr + 12);
            float4 q4 = *(const float4*)(hr + 16);
            float hv[20] = {q0.x,q0.y,q0.z,q0.w, q1.x,q1.y,q1.z,q1.w,
                            q2.x,q2.y,q2.z,q2.w, q3.x,q3.y,q3.z,q3.w,
                            q4.x,q4.y,q4.z,q4.w};

            if (up == 1 && t > 0) {               // out[t-1] for row B
                u64 oa = 0ULL;
#pragma unroll
                for (int j = 0; j < 10; ++j)
                    oa = fma2(w2q[j], pk(hv[2*j], hv[2*j+1]), oa);
                float lo, hi; upk(oa, lo, hi);
                g_outT[(size_t)(t - 1) * B_DIM + rowB] = lo + hi + b2_s;
            }

            u64 x2 = pk(xB, xB);
            u64 ai = fma2(x2, u_i, v_i), af = fma2(x2, u_f, v_f);
            u64 ag = fma2(x2, u_g, v_g), ao = fma2(x2, u_o, v_o);
#pragma unroll
            for (int u = 0; u < UPIN; ++u) {
                u64 hp = pk(hv[u], hv[u]);
                ai = fma2(wpa[u].x, hp, ai);  af = fma2(wpa[u].y, hp, af);
                ag = fma2(wpb[u].x, hp, ag);  ao = fma2(wpb[u].y, hp, ao);
            }
#pragma unroll
            for (int u = UPIN; u < H; ++u) {
                u64 hp = pk(hv[u], hv[u]);
                ulonglong2 wa = *(const ulonglong2*)&WP_s[u][up4];
                ulonglong2 wb = *(const ulonglong2*)&WP_s[u][up4 + 2];
                ai = fma2(wa.x, hp, ai);  af = fma2(wa.y, hp, af);
                ag = fma2(wb.x, hp, ag);  ao = fma2(wb.y, hp, ao);
            }
            float i0,i1,f0,f1,g0,g1,o0,o1;
            upk(ai,i0,i1); upk(af,f0,f1); upk(ag,g0,g1); upk(ao,o0,o1);
            float c0,c1; upk(cB,c0,c1);
            float h0,h1;
            cell(i0,f0,g0,o0,c0,h0);
            cell(i1,f1,g1,o1,c1,h1);
            cB = pk(c0,c1);
            *(u64*)&h_s[nxt][1][lane][2*up] = pk(h0,h1);
        }

        // single barrier per step: publish h(t+1), protect buffer swap
        __syncthreads();

        xA = xAn; xB = xBn;
    }

    // final out[T-1] from buffer (T_DIM & 1); last __syncthreads covers it
    {
        const int cur = T_DIM & 1;
        if (up < 2) {
            const float* hr = &h_s[cur][up][lane][0];
            u64 oa = 0ULL;
#pragma unroll
            for (int j = 0; j < 10; ++j)
                oa = fma2(w2q[j], pk(hr[2*j], hr[2*j+1]), oa);
            float lo, hi; upk(oa, lo, hi);
            int row = (up == 0) ? rowA : rowB;
            g_outT[(size_t)(T_DIM - 1) * B_DIM + row] = lo + hi + b2_s;
        }
    }
}

// ---------------- launcher ----------------
extern "C" void kernel_launch(void* const* d_in, const int* in_sizes, int n_in,
                              void* d_out, int out_size)
{
    const float* x    = (const float*)d_in[0];
    const float* W1   = (const float*)d_in[1];
    const float* b1   = (const float*)d_in[2];
    const float* W_ih = (const float*)d_in[3];
    const float* W_hh = (const float*)d_in[4];
    const float* b_ih = (const float*)d_in[5];
    const float* b_hh = (const float*)d_in[6];
    const float* W2   = (const float*)d_in[7];
    const float* b2   = (const float*)d_in[8];
    float* out = (float*)d_out;

    (void)in_sizes; (void)n_in; (void)out_size;

    // x[B][T] -> g_xT[T][B]
    transpose_in<<<dim3(T_DIM / 32, B_DIM / 32), dim3(32, 8)>>>(x);

    // recurrent scan: 128 CTAs x 320 threads, dual independent half-steps
    lstm_kernel<<<B_DIM / CTA_ROWS, NTHR>>>(W1, b1, W_ih, W_hh, b_ih, b_hh, W2, b2);

    // g_outT[T][B] -> out[B][T]
    transpose_out<<<dim3(B_DIM / 32, T_DIM / 32), dim3(32, 8)>>>(out);
}

// round 11
// speedup vs baseline: 2.6873x; 2.6873x over previous
#include <cuda_runtime.h>

// Problem dims (fixed by reference setup_inputs)
#define B_DIM 8192
#define T_DIM 2048
#define H     20
#define CTA_ROWS 64       // batch rows per CTA
#define NTHR  256         // 8 warps; warps 0-3 own 3 units, warps 4-7 own 2
#define PSRC  8           // source units pinned in registers

typedef unsigned long long u64;

// Scratch (allocation-free rule: __device__ globals)
__device__ float g_xT[(size_t)T_DIM * B_DIM];   // x transposed: [t][b]
__device__ float g_outT[(size_t)T_DIM * B_DIM]; // out transposed: [t][b]

// ---------------- f32x2 helpers ----------------
__device__ __forceinline__ u64 pk(float lo, float hi) {
    u64 r; asm("mov.b64 %0,{%1,%2};" : "=l"(r) : "f"(lo), "f"(hi)); return r;
}
__device__ __forceinline__ void upk(u64 v, float& lo, float& hi) {
    asm("mov.b64 {%0,%1},%2;" : "=f"(lo), "=f"(hi) : "l"(v));
}
__device__ __forceinline__ u64 fma2(u64 a, u64 b, u64 c) {
    u64 d; asm("fma.rn.f32x2 %0,%1,%2,%3;" : "=l"(d) : "l"(a), "l"(b), "l"(c)); return d;
}
__device__ __forceinline__ float tanh_a(float x) {
    float r; asm("tanh.approx.f32 %0,%1;" : "=f"(r) : "f"(x)); return r;
}

// LSTM cell via MUFU.TANH: 5 MUFU + ~9 FMA-pipe ops.
__device__ __forceinline__ void cell(float ig, float fg, float gg, float og,
                                     float& c, float& h) {
    float si = fmaf(0.5f, tanh_a(0.5f * ig), 0.5f);
    float sf = fmaf(0.5f, tanh_a(0.5f * fg), 0.5f);
    float so = fmaf(0.5f, tanh_a(0.5f * og), 0.5f);
    float tg = tanh_a(gg);
    float cn = sf * c + si * tg;
    float tc = tanh_a(cn);
    c = cn;
    h = so * tc;
}

// ---------------- transposes ----------------
__global__ void transpose_in(const float* __restrict__ in) {
    __shared__ float tile[32][33];
    int c0 = blockIdx.x * 32, r0 = blockIdx.y * 32;
    int tx = threadIdx.x, ty = threadIdx.y;
#pragma unroll
    for (int i = 0; i < 32; i += 8)
        tile[ty + i][tx] = in[(size_t)(r0 + ty + i) * T_DIM + c0 + tx];
    __syncthreads();
#pragma unroll
    for (int i = 0; i < 32; i += 8)
        g_xT[(size_t)(c0 + ty + i) * B_DIM + r0 + tx] = tile[tx][ty + i];
}

__global__ void transpose_out(float* __restrict__ out) {
    __shared__ float tile[32][33];
    int c0 = blockIdx.x * 32, r0 = blockIdx.y * 32;
    int tx = threadIdx.x, ty = threadIdx.y;
#pragma unroll
    for (int i = 0; i < 32; i += 8)
        tile[ty + i][tx] = g_outT[(size_t)(r0 + ty + i) * B_DIM + c0 + tx];
    __syncthreads();
#pragma unroll
    for (int i = 0; i < 32; i += 8)
        out[(size_t)(c0 + ty + i) * T_DIM + r0 + tx] = tile[tx][ty + i];
}

// Slot -> (gate-row ka, gate-row kb) mapping shared by setup paths.
// Warps 0-3: units ub=3w,3w+1,3w+2. Slots 0-3: gate s of pair (ub,ub+1).
//            Slot 4: (i,f) of ub+2. Slot 5: (g,o) of ub+2.
// Warps 4-7: units ub=12+2(w-4). Slots 0-3 only.
__device__ __forceinline__ bool slot_rows(int w, int s, int& ka, int& kb) {
    if (w < 4) {
        int ub = 3 * w;
        if (s < 4)      { ka = s * H + ub;     kb = ka + 1; }
        else if (s == 4){ ka = 0 * H + ub + 2; kb = 1 * H + ub + 2; }
        else            { ka = 2 * H + ub + 2; kb = 3 * H + ub + 2; }
        return true;
    } else {
        int ub = 12 + 2 * (w - 4);
        if (s < 4) { ka = s * H + ub; kb = ka + 1; return true; }
        return false;
    }
}

// ---------------- main persistent LSTM kernel ----------------
// 128 CTAs x 256 threads (8 warps). CTA owns 64 rows; lane owns rows
// (2*lane, 2*lane+1); f32x2 packs units (or gates, for the solo unit).
// Asymmetric unit assignment balances SMSPs exactly: SMSP k runs wid k
// (3 units, 480 cyc FMA) + wid k+4 (2 units, 360 cyc) = 840 cyc each.
// PSRC source units pinned in registers; one __syncthreads per step.
__global__ __launch_bounds__(NTHR, 1) void lstm_kernel(
    const float* __restrict__ W1, const float* __restrict__ b1,
    const float* __restrict__ W_ih, const float* __restrict__ W_hh,
    const float* __restrict__ b_ih, const float* __restrict__ b_hh,
    const float* __restrict__ W2, const float* __restrict__ b2)
{
    __shared__ __align__(16) u64 WQ[H][8][6];     // [src][warp][slot]  7.7 KB
    __shared__ __align__(16) u64 uvu[8][6], uvv[8][6];
    __shared__ u64 w2p[H];                        // (W2[u], W2[u])
    __shared__ float b2_s;
    __shared__ __align__(8) float h_s[2][H][CTA_ROWS];  // 10.2 KB

    const int tid  = threadIdx.x;
    const int lane = tid & 31;
    const int wid  = tid >> 5;
    const int rowbase = blockIdx.x * CTA_ROWS;
    const int rA = 2 * lane;

    // --- one-time setup ---
    for (int i = tid; i < H * 48; i += NTHR) {
        int src = i / 48, r = i % 48, w = r / 6, s = r % 6;
        int ka, kb;
        WQ[src][w][s] = slot_rows(w, s, ka, kb)
            ? pk(W_hh[ka * H + src], W_hh[kb * H + src]) : 0ULL;
    }
    if (tid < 48) {
        int w = tid / 6, s = tid % 6, ka, kb;
        if (slot_rows(w, s, ka, kb)) {
            float sua = 0.f, sva = 0.f, sub = 0.f, svb = 0.f;
            for (int u = 0; u < H; ++u) {
                sua += W_ih[ka * H + u] * W1[u];
                sva += W_ih[ka * H + u] * b1[u];
                sub += W_ih[kb * H + u] * W1[u];
                svb += W_ih[kb * H + u] * b1[u];
            }
            uvu[w][s] = pk(sua, sub);
            uvv[w][s] = pk(sva + b_ih[ka] + b_hh[ka], svb + b_ih[kb] + b_hh[kb]);
        } else { uvu[w][s] = 0ULL; uvv[w][s] = 0ULL; }
    }
    if (tid < H) { float wv = W2[tid]; w2p[tid] = pk(wv, wv); }
    if (tid == 0) b2_s = b2[0];
    for (int i = tid; i < 2 * H * CTA_ROWS; i += NTHR) h_s[0][0][i] = 0.f;
    __syncthreads();

    const int ub = (wid < 4) ? 3 * wid : 12 + 2 * (wid - 4);

    // per-warp register tables
    u64 uu[6], vv[6];
#pragma unroll
    for (int s = 0; s < 6; ++s) { uu[s] = uvu[wid][s]; vv[s] = uvv[wid][s]; }

    // pinned weights for sources [0, PSRC): 48 u64 = 96 regs (heavy path)
    u64 wp[PSRC][6];
#pragma unroll
    for (int u = 0; u < PSRC; ++u)
#pragma unroll
        for (int s = 0; s < 6; ++s) wp[u][s] = WQ[u][wid][s];

    u64 c2[3] = {0ULL, 0ULL, 0ULL};   // cell state per owned unit: (rowA, rowB)

    float2 xv = *(const float2*)(g_xT + rowbase + rA);

    for (int t = 0; t < T_DIM; ++t) {
        const int cur = t & 1, nxt = cur ^ 1;

        float2 xnext = xv;
        if (t + 1 < T_DIM)
            xnext = *(const float2*)(g_xT + (size_t)(t + 1) * B_DIM + rowbase + rA);

        // ---- preload full h vector (u64 = (h[rowA], h[rowB])) ----
        u64 h2[H];
#pragma unroll
        for (int u = 0; u < H; ++u)
            h2[u] = *(const u64*)&h_s[cur][u][rA];

        // ---- out[t-1]: LIGHT warp 4 (reuses its h2 registers) ----
        if (wid == 4 && t > 0) {
            u64 oacc = pk(b2_s, b2_s);
#pragma unroll
            for (int u = 0; u < H; ++u)
                oacc = fma2(w2p[u], h2[u], oacc);
            float o0, o1; upk(oacc, o0, o1);
            *(float2*)(g_outT + (size_t)(t - 1) * B_DIM + rowbase + rA) =
                make_float2(o0, o1);
        }

        u64 xA2 = pk(xv.x, xv.x), xB2 = pk(xv.y, xv.y);

        if (wid < 4) {
            // ===== heavy path: 3 units, 6 slots =====
            u64 aA[6], aB[6];
#pragma unroll
            for (int s = 0; s < 6; ++s) {
                aA[s] = fma2(xA2, uu[s], vv[s]);
                aB[s] = fma2(xB2, uu[s], vv[s]);
            }
#pragma unroll
            for (int u = 0; u < PSRC; ++u) {
                float hA, hB; upk(h2[u], hA, hB);
                u64 hpA = pk(hA, hA), hpB = pk(hB, hB);
#pragma unroll
                for (int s = 0; s < 6; ++s) {
                    aA[s] = fma2(wp[u][s], hpA, aA[s]);
                    aB[s] = fma2(wp[u][s], hpB, aB[s]);
                }
            }
#pragma unroll
            for (int u = PSRC; u < H; ++u) {
                float hA, hB; upk(h2[u], hA, hB);
                u64 hpA = pk(hA, hA), hpB = pk(hB, hB);
                ulonglong2 q0 = *(const ulonglong2*)&WQ[u][wid][0];
                ulonglong2 q1 = *(const ulonglong2*)&WQ[u][wid][2];
                ulonglong2 q2 = *(const ulonglong2*)&WQ[u][wid][4];
                aA[0] = fma2(q0.x, hpA, aA[0]);  aB[0] = fma2(q0.x, hpB, aB[0]);
                aA[1] = fma2(q0.y, hpA, aA[1]);  aB[1] = fma2(q0.y, hpB, aB[1]);
                aA[2] = fma2(q1.x, hpA, aA[2]);  aB[2] = fma2(q1.x, hpB, aB[2]);
                aA[3] = fma2(q1.y, hpA, aA[3]);  aB[3] = fma2(q1.y, hpB, aB[3]);
                aA[4] = fma2(q2.x, hpA, aA[4]);  aB[4] = fma2(q2.x, hpB, aB[4]);
                aA[5] = fma2(q2.y, hpA, aA[5]);  aB[5] = fma2(q2.y, hpB, aB[5]);
            }
            // cells: units ub, ub+1 from slots 0-3; unit ub+2 from slots 4,5
            float iA0,iA1,fA0,fA1,gA0,gA1,oA0,oA1;
            float iB0,iB1,fB0,fB1,gB0,gB1,oB0,oB1;
            upk(aA[0],iA0,iA1); upk(aA[1],fA0,fA1);
            upk(aA[2],gA0,gA1); upk(aA[3],oA0,oA1);
            upk(aB[0],iB0,iB1); upk(aB[1],fB0,fB1);
            upk(aB[2],gB0,gB1); upk(aB[3],oB0,oB1);
            float ifA0,ifA1,goA0,goA1, ifB0,ifB1,goB0,goB1;
            upk(aA[4],ifA0,ifA1); upk(aA[5],goA0,goA1);
            upk(aB[4],ifB0,ifB1); upk(aB[5],goB0,goB1);

            float cA, cB, hA, hB;
            upk(c2[0], cA, cB);
            cell(iA0, fA0, gA0, oA0, cA, hA);
            cell(iB0, fB0, gB0, oB0, cB, hB);
            c2[0] = pk(cA, cB);
            *(u64*)&h_s[nxt][ub][rA] = pk(hA, hB);

            upk(c2[1], cA, cB);
            cell(iA1, fA1, gA1, oA1, cA, hA);
            cell(iB1, fB1, gB1, oB1, cB, hB);
            c2[1] = pk(cA, cB);
            *(u64*)&h_s[nxt][ub + 1][rA] = pk(hA, hB);

            upk(c2[2], cA, cB);
            cell(ifA0, ifA1, goA0, goA1, cA, hA);
            cell(ifB0, ifB1, goB0, goB1, cB, hB);
            c2[2] = pk(cA, cB);
            *(u64*)&h_s[nxt][ub + 2][rA] = pk(hA, hB);
        } else {
            // ===== light path: 2 units, 4 slots =====
            u64 aA[4], aB[4];
#pragma unroll
            for (int s = 0; s < 4; ++s) {
                aA[s] = fma2(xA2, uu[s], vv[s]);
                aB[s] = fma2(xB2, uu[s], vv[s]);
            }
#pragma unroll
            for (int u = 0; u < PSRC; ++u) {
                float hA, hB; upk(h2[u], hA, hB);
                u64 hpA = pk(hA, hA), hpB = pk(hB, hB);
#pragma unroll
                for (int s = 0; s < 4; ++s) {
                    aA[s] = fma2(wp[u][s], hpA, aA[s]);
                    aB[s] = fma2(wp[u][s], hpB, aB[s]);
                }
            }
#pragma unroll
            for (int u = PSRC; u < H; ++u) {
                float hA, hB; upk(h2[u], hA, hB);
                u64 hpA = pk(hA, hA), hpB = pk(hB, hB);
                ulonglong2 q0 = *(const ulonglong2*)&WQ[u][wid][0];
                ulonglong2 q1 = *(const ulonglong2*)&WQ[u][wid][2];
                aA[0] = fma2(q0.x, hpA, aA[0]);  aB[0] = fma2(q0.x, hpB, aB[0]);
                aA[1] = fma2(q0.y, hpA, aA[1]);  aB[1] = fma2(q0.y, hpB, aB[1]);
                aA[2] = fma2(q1.x, hpA, aA[2]);  aB[2] = fma2(q1.x, hpB, aB[2]);
                aA[3] = fma2(q1.y, hpA, aA[3]);  aB[3] = fma2(q1.y, hpB, aB[3]);
            }
            float iA0,iA1,fA0,fA1,gA0,gA1,oA0,oA1;
            float iB0,iB1,fB0,fB1,gB0,gB1,oB0,oB1;
            upk(aA[0],iA0,iA1); upk(aA[1],fA0,fA1);
            upk(aA[2],gA0,gA1); upk(aA[3],oA0,oA1);
            upk(aB[0],iB0,iB1); upk(aB[1],fB0,fB1);
            upk(aB[2],gB0,gB1); upk(aB[3],oB0,oB1);

            float cA, cB, hA, hB;
            upk(c2[0], cA, cB);
            cell(iA0, fA0, gA0, oA0, cA, hA);
            cell(iB0, fB0, gB0, oB0, cB, hB);
            c2[0] = pk(cA, cB);
            *(u64*)&h_s[nxt][ub][rA] = pk(hA, hB);

            upk(c2[1], cA, cB);
            cell(iA1, fA1, gA1, oA1, cA, hA);
            cell(iB1, fB1, gB1, oB1, cB, hB);
            c2[1] = pk(cA, cB);
            *(u64*)&h_s[nxt][ub + 1][rA] = pk(hA, hB);
        }

        // single barrier per step (top-level: all 256 threads arrive)
        __syncthreads();

        xv = xnext;
    }

    // final out[T-1] from buffer (T_DIM & 1)
    if (wid == 4) {
        const int cur = T_DIM & 1;
        u64 oacc = pk(b2_s, b2_s);
#pragma unroll
        for (int u = 0; u < H; ++u)
            oacc = fma2(w2p[u], *(const u64*)&h_s[cur][u][rA], oacc);
        float o0, o1; upk(oacc, o0, o1);
        *(float2*)(g_outT + (size_t)(T_DIM - 1) * B_DIM + rowbase + rA) =
            make_float2(o0, o1);
    }
}

// ---------------- launcher ----------------
extern "C" void kernel_launch(void* const* d_in, const int* in_sizes, int n_in,
                              void* d_out, int out_size)
{
    const float* x    = (const float*)d_in[0];
    const float* W1   = (const float*)d_in[1];
    const float* b1   = (const float*)d_in[2];
    const float* W_ih = (const float*)d_in[3];
    const float* W_hh = (const float*)d_in[4];
    const float* b_ih = (const float*)d_in[5];
    const float* b_hh = (const float*)d_in[6];
    const float* W2   = (const float*)d_in[7];
    const float* b2   = (const float*)d_in[8];
    float* out = (float*)d_out;

    (void)in_sizes; (void)n_in; (void)out_size;

    // x[B][T] -> g_xT[T][B]
    transpose_in<<<dim3(T_DIM / 32, B_DIM / 32), dim3(32, 8)>>>(x);

    // recurrent scan: 128 CTAs x 256 threads, SMSP-balanced unit assignment
    lstm_kernel<<<B_DIM / CTA_ROWS, NTHR>>>(W1, b1, W_ih, W_hh, b_ih, b_hh, W2, b2);

    // g_outT[T][B] -> out[B][T]
    transpose_out<<<dim3(B_DIM / 32, T_DIM / 32), dim3(32, 8)>>>(out);
}